// round 1
// baseline (speedup 1.0000x reference)
#include <cuda_runtime.h>

// BFP quantize: block = channel vector (C=256) at each (n,h,w), NCHW fp32.
// shape (N=64, C=256, H=56, W=56), HW = 3136 floats = 784 float4.
//
// Tile: 64 hw positions (16 float4) x 256 channels, handled by one 512-thread CTA.
// Thread t: hw4 = t & 15 (fixed float4 column), cbase = t >> 4 (0..31),
//           channels c = cbase + 32k, k = 0..7  -> 8 float4 in registers.
// Loads are coalesced (16 consecutive lanes cover 256B contiguous per channel row).
// Input read once from HBM; data stays in registers across the reduction.

#define THREADS 512
#define CPT 8            // channels per thread = 256 / 32
#define TILE_V4 16       // float4 per tile (64 floats of hw)

__global__ void __launch_bounds__(THREADS)
bfp_quant_kernel(const float4* __restrict__ in, float4* __restrict__ out,
                 int hw_v4 /*784*/, int c_dim /*256*/) {
    __shared__ float4 pm[16][16];   // [warp][hw4] partial maxes
    __shared__ float s_delta[64];
    __shared__ float s_inv[64];

    const int t     = threadIdx.x;
    const int hw4   = t & 15;        // which float4 column in the tile
    const int cbase = t >> 4;        // 0..31
    const int tile  = blockIdx.x;    // 0..48
    const int n     = blockIdx.y;    // 0..63

    // float4-element index of this thread's first load
    const int base = n * (c_dim * hw_v4) + tile * TILE_V4 + hw4;
    const int cstride = 32 * hw_v4;  // 32 channels apart per k-step

    float4 v[CPT];
    float mx = 0.f, my = 0.f, mz = 0.f, mw = 0.f;
#pragma unroll
    for (int k = 0; k < CPT; k++) {
        v[k] = in[base + cbase * hw_v4 + k * cstride];
        mx = fmaxf(mx, fabsf(v[k].x));
        my = fmaxf(my, fabsf(v[k].y));
        mz = fmaxf(mz, fabsf(v[k].z));
        mw = fmaxf(mw, fabsf(v[k].w));
    }

    // Within a warp, lanes l and l^16 share the same hw4 (cbase differs) -> one bfly.
    mx = fmaxf(mx, __shfl_xor_sync(0xffffffffu, mx, 16));
    my = fmaxf(my, __shfl_xor_sync(0xffffffffu, my, 16));
    mz = fmaxf(mz, __shfl_xor_sync(0xffffffffu, mz, 16));
    mw = fmaxf(mw, __shfl_xor_sync(0xffffffffu, mw, 16));

    const int w = t >> 5;            // warp id 0..15
    if ((t & 31) < 16) pm[w][hw4] = make_float4(mx, my, mz, mw);
    __syncthreads();

    if (t < 16) {
        float4 a = pm[0][t];
#pragma unroll
        for (int ww = 1; ww < 16; ww++) {
            float4 b = pm[ww][t];
            a.x = fmaxf(a.x, b.x);
            a.y = fmaxf(a.y, b.y);
            a.z = fmaxf(a.z, b.z);
            a.w = fmaxf(a.w, b.w);
        }
        float ma[4] = {a.x, a.y, a.z, a.w};
#pragma unroll
        for (int c = 0; c < 4; c++) {
            int e;
            (void)frexpf(ma[c], &e);              // max_abs = m * 2^e, m in [0.5,1)
            s_delta[4 * t + c] = ldexpf(1.0f, e - 3);   // 2^(e-3), exact
            s_inv[4 * t + c]   = ldexpf(1.0f, 3 - e);   // 2^(3-e), exact
        }
    }
    __syncthreads();

    const float dx = s_delta[4 * hw4 + 0], ix = s_inv[4 * hw4 + 0];
    const float dy = s_delta[4 * hw4 + 1], iy = s_inv[4 * hw4 + 1];
    const float dz = s_delta[4 * hw4 + 2], iz = s_inv[4 * hw4 + 2];
    const float dw = s_delta[4 * hw4 + 3], iw = s_inv[4 * hw4 + 3];

#pragma unroll
    for (int k = 0; k < CPT; k++) {
        float4 q;
        q.x = truncf(v[k].x * ix) * dx;
        q.y = truncf(v[k].y * iy) * dy;
        q.z = truncf(v[k].z * iz) * dz;
        q.w = truncf(v[k].w * iw) * dw;
        out[base + cbase * hw_v4 + k * cstride] = q;
    }
}

extern "C" void kernel_launch(void* const* d_in, const int* in_sizes, int n_in,
                              void* d_out, int out_size) {
    (void)n_in; (void)out_size;
    const float4* in = (const float4*)d_in[0];
    float4* out = (float4*)d_out;

    const int C = 256;
    const int HW = 56 * 56;          // 3136
    const int hw_v4 = HW / 4;        // 784
    const int total = in_sizes[0];   // 51380224
    const int N = total / (C * HW);  // 64

    dim3 grid(hw_v4 / TILE_V4, N);   // (49, 64)
    bfp_quant_kernel<<<grid, THREADS>>>(in, out, hw_v4, C);
}

// round 2
// speedup vs baseline: 1.1656x; 1.1656x over previous
#include <cuda_runtime.h>

// BFP quantize: block = channel vector (C=256) at each (n,h,w), NCHW fp32.
// shape (N=64, C=256, H=56, W=56), HW = 3136 floats = 784 float4.
//
// Tile: 16 hw positions (4 float4 columns) x 256 channels per 512-thread CTA.
// Thread t: hw4 = t & 3 (float4 column), cbase = t >> 2 (0..127),
//           channels c = cbase + 128k, k = 0..1  -> only 2 float4 in registers.
// 4 consecutive lanes cover 64B contiguous (2 full sectors) per channel row.
// Low register count -> 3 CTAs/SM so load/reduce/store phases of different
// CTAs overlap and DRAM stays busy.

#define THREADS 512
#define CPT 2            // channels per thread = 256 / 128
#define TILE_V4 4        // float4 columns per tile (16 floats of hw)

__global__ void __launch_bounds__(THREADS, 3)
bfp_quant_kernel(const float4* __restrict__ in, float4* __restrict__ out,
                 int hw_v4 /*784*/, int c_dim /*256*/) {
    __shared__ float pm[16][16];    // [warp][hw4*4 + comp] partial maxes
    __shared__ float s_delta[16];
    __shared__ float s_inv[16];

    const int t     = threadIdx.x;
    const int hw4   = t & 3;         // float4 column in tile
    const int cbase = t >> 2;        // 0..127
    const int tile  = blockIdx.x;    // 0..195
    const int n     = blockIdx.y;    // 0..63

    const int base    = n * (c_dim * hw_v4) + cbase * hw_v4 + tile * TILE_V4 + hw4;
    const int cstride = 128 * hw_v4;

    float4 v[CPT];
    float mx, my, mz, mw;
    v[0] = __ldcs(in + base);
    v[1] = __ldcs(in + base + cstride);
    mx = fmaxf(fabsf(v[0].x), fabsf(v[1].x));
    my = fmaxf(fabsf(v[0].y), fabsf(v[1].y));
    mz = fmaxf(fabsf(v[0].z), fabsf(v[1].z));
    mw = fmaxf(fabsf(v[0].w), fabsf(v[1].w));

    // Butterfly over lanes sharing hw4 (xor 4, 8, 16 all preserve lane&3).
#pragma unroll
    for (int s = 4; s <= 16; s <<= 1) {
        mx = fmaxf(mx, __shfl_xor_sync(0xffffffffu, mx, s));
        my = fmaxf(my, __shfl_xor_sync(0xffffffffu, my, s));
        mz = fmaxf(mz, __shfl_xor_sync(0xffffffffu, mz, s));
        mw = fmaxf(mw, __shfl_xor_sync(0xffffffffu, mw, s));
    }

    const int w = t >> 5;            // warp id 0..15
    if ((t & 31) < 4) {              // lanes 0..3 hold hw4 = 0..3
        pm[w][hw4 * 4 + 0] = mx;
        pm[w][hw4 * 4 + 1] = my;
        pm[w][hw4 * 4 + 2] = mz;
        pm[w][hw4 * 4 + 3] = mw;
    }
    __syncthreads();

    if (t < 16) {                    // t = hw4*4 + comp
        float m = pm[0][t];
#pragma unroll
        for (int ww = 1; ww < 16; ww++) m = fmaxf(m, pm[ww][t]);
        int e;
        (void)frexpf(m, &e);                    // max_abs = mant * 2^e, mant in [0.5,1)
        s_delta[t] = ldexpf(1.0f, e - 3);       // 2^(e-3), exact
        s_inv[t]   = ldexpf(1.0f, 3 - e);       // 2^(3-e), exact
    }
    __syncthreads();

    const float dx = s_delta[hw4 * 4 + 0], ix = s_inv[hw4 * 4 + 0];
    const float dy = s_delta[hw4 * 4 + 1], iy = s_inv[hw4 * 4 + 1];
    const float dz = s_delta[hw4 * 4 + 2], iz = s_inv[hw4 * 4 + 2];
    const float dw = s_delta[hw4 * 4 + 3], iw = s_inv[hw4 * 4 + 3];

#pragma unroll
    for (int k = 0; k < CPT; k++) {
        float4 q;
        q.x = truncf(v[k].x * ix) * dx;
        q.y = truncf(v[k].y * iy) * dy;
        q.z = truncf(v[k].z * iz) * dz;
        q.w = truncf(v[k].w * iw) * dw;
        __stcs(out + base + k * cstride, q);
    }
}

extern "C" void kernel_launch(void* const* d_in, const int* in_sizes, int n_in,
                              void* d_out, int out_size) {
    (void)n_in; (void)out_size;
    const float4* in = (const float4*)d_in[0];
    float4* out = (float4*)d_out;

    const int C = 256;
    const int HW = 56 * 56;          // 3136
    const int hw_v4 = HW / 4;        // 784
    const int total = in_sizes[0];   // 51380224
    const int N = total / (C * HW);  // 64

    dim3 grid(hw_v4 / TILE_V4, N);   // (196, 64)
    bfp_quant_kernel<<<grid, THREADS>>>(in, out, hw_v4, C);
}

// round 4
// speedup vs baseline: 1.4570x; 1.2500x over previous
#include <cuda_runtime.h>

// BFP quantize: block = channel vector (C=256) at each (n,h,w), NCHW fp32.
// shape (N=64, C=256, H=56, W=56), HW = 3136 floats = 784 float4.
//
// Tile: 16 hw positions (4 float4 columns) x 256 channels per 256-thread CTA.
// Thread t: hw4 = t & 3 (float4 column), cbase = t >> 2 (0..63),
//           channels c = cbase + 64k, k = 0..3  -> 4 float4 in registers (MLP=4).
// 4 consecutive lanes cover 64B contiguous (2 full sectors) per channel row.
// 5 CTAs/SM at independent phases keep DRAM busy through the reduce barriers.

#define THREADS 256
#define CPT 4            // channels per thread = 256 / 64
#define TILE_V4 4        // float4 columns per tile (16 floats of hw)

__global__ void __launch_bounds__(THREADS, 5)
bfp_quant_kernel(const float4* __restrict__ in, float4* __restrict__ out,
                 int hw_v4 /*784*/, int c_dim /*256*/) {
    __shared__ float4 pm4[8][4];    // [warp][hw4] partial maxes (x,y,z,w = 4 hw)
    __shared__ float s_delta[16];
    __shared__ float s_inv[16];

    const int t     = threadIdx.x;
    const int hw4   = t & 3;         // float4 column in tile
    const int cbase = t >> 2;        // 0..63
    const int tile  = blockIdx.x;    // 0..195
    const int n     = blockIdx.y;    // 0..63

    const int base    = n * (c_dim * hw_v4) + cbase * hw_v4 + tile * TILE_V4 + hw4;
    const int cstride = 64 * hw_v4;

    // Front-load 4 independent 16B loads (MLP=4).
    float4 v[CPT];
#pragma unroll
    for (int k = 0; k < CPT; k++) v[k] = __ldcs(in + base + k * cstride);

    float mx = 0.f, my = 0.f, mz = 0.f, mw = 0.f;
#pragma unroll
    for (int k = 0; k < CPT; k++) {
        mx = fmaxf(mx, fabsf(v[k].x));
        my = fmaxf(my, fabsf(v[k].y));
        mz = fmaxf(mz, fabsf(v[k].z));
        mw = fmaxf(mw, fabsf(v[k].w));
    }

    // Butterfly over the 8 lanes sharing hw4 (xor 4, 8, 16 preserve lane&3).
#pragma unroll
    for (int s = 4; s <= 16; s <<= 1) {
        mx = fmaxf(mx, __shfl_xor_sync(0xffffffffu, mx, s));
        my = fmaxf(my, __shfl_xor_sync(0xffffffffu, my, s));
        mz = fmaxf(mz, __shfl_xor_sync(0xffffffffu, mz, s));
        mw = fmaxf(mw, __shfl_xor_sync(0xffffffffu, mw, s));
    }

    const int w = t >> 5;            // warp id 0..7
    if ((t & 31) < 4) {              // lanes 0..3 hold hw4 = 0..3
        pm4[w][hw4] = make_float4(mx, my, mz, mw);
    }
    __syncthreads();

    if (t < 16) {                    // t = hw4*4 + comp, scalar hw position
        const float* pm = &pm4[0][0].x;
        float m = pm[t];
#pragma unroll
        for (int ww = 1; ww < 8; ww++) m = fmaxf(m, pm[ww * 16 + t]);

        // frexp(m) = mant * 2^e; for normal m, e = E - 126 (E = biased exponent).
        // delta = 2^(e-3) = 2^(E-129)  -> biased exp field E-2.
        // inv   = 2^(3-e) = 2^(129-E)  -> biased exp field 256-E.
        unsigned b = __float_as_uint(m);         // m >= 0
        unsigned E = b >> 23;
        float d, iv;
        if (b == 0u) {
            d = 0.f; iv = 0.f;                   // zero block -> output 0
        } else if (E >= 3u && E <= 253u) {       // fast path: fields stay in range
            d  = __uint_as_float((E - 2u)   << 23);
            iv = __uint_as_float((256u - E) << 23);
        } else {                                 // denormal/extreme: exact fallback
            int e;
            (void)frexpf(m, &e);
            d  = ldexpf(1.0f, e - 3);
            iv = ldexpf(1.0f, 3 - e);
        }
        s_delta[t] = d;
        s_inv[t]   = iv;
    }
    __syncthreads();

    const float dx = s_delta[hw4 * 4 + 0], ix = s_inv[hw4 * 4 + 0];
    const float dy = s_delta[hw4 * 4 + 1], iy = s_inv[hw4 * 4 + 1];
    const float dz = s_delta[hw4 * 4 + 2], iz = s_inv[hw4 * 4 + 2];
    const float dw = s_delta[hw4 * 4 + 3], iw = s_inv[hw4 * 4 + 3];

#pragma unroll
    for (int k = 0; k < CPT; k++) {
        float4 q;
        q.x = truncf(v[k].x * ix) * dx;
        q.y = truncf(v[k].y * iy) * dy;
        q.z = truncf(v[k].z * iz) * dz;
        q.w = truncf(v[k].w * iw) * dw;
        __stcs(out + base + k * cstride, q);
    }
}

extern "C" void kernel_launch(void* const* d_in, const int* in_sizes, int n_in,
                              void* d_out, int out_size) {
    (void)n_in; (void)out_size;
    const float4* in = (const float4*)d_in[0];
    float4* out = (float4*)d_out;

    const int C = 256;
    const int HW = 56 * 56;          // 3136
    const int hw_v4 = HW / 4;        // 784
    const int total = in_sizes[0];   // 51380224
    const int N = total / (C * HW);  // 64

    dim3 grid(hw_v4 / TILE_V4, N);   // (196, 64)
    bfp_quant_kernel<<<grid, THREADS>>>(in, out, hw_v4, C);
}